// round 16
// baseline (speedup 1.0000x reference)
#include <cuda_runtime.h>

#define TT 64
#define FULL 0xffffffffu

__device__ __forceinline__ float sx(float v, int m) { return __shfl_xor_sync(FULL, v, m); }
__device__ __forceinline__ float tanhap(float v) {
    float r; asm("tanh.approx.f32 %0, %1;" : "=f"(r) : "f"(v)); return r;
}
// basis coefficient: factor p (0:cos(alpha),1:sin(alpha)), basis bit b (0->cY,1->sY)
__device__ __forceinline__ float fco(int p, int b, float cg, float sg) {
    return p ? (b ? cg : sg) : (b ? -sg : cg);
}

// One warp = TWO elements (sequential dual, phase-interleaved).
// 32-lane closed-form layout per element: lane = g*8 + sub.
__global__ void __launch_bounds__(128)
qlstmcf32d(const float* __restrict__ x,
           const float* __restrict__ w_in,  const float* __restrict__ b_in,
           const float* __restrict__ w_out, const float* __restrict__ b_out,
           const float* __restrict__ wq_f,  const float* __restrict__ wq_i,
           const float* __restrict__ wq_u,  const float* __restrict__ wq_o,
           const float* __restrict__ w_fc,  const float* __restrict__ b_fc,
           float* __restrict__ out, int B)
{
    const int lane = threadIdx.x & 31;
    const int wib  = threadIdx.x >> 5;     // warp in block (0..3)
    const int g    = lane >> 3;
    const int sub  = lane & 7;
    const int b8   = lane & ~7;
    int eA = blockIdx.x * 8 + wib * 2;
    int eB = eA + 1;
    const bool okA = (eA < B), okB = (eB < B);
    if (eA >= B) eA = B - 1;
    if (eB >= B) eB = B - 1;
    const int slotA = wib * 2, slotB = wib * 2 + 1;

    __shared__ float sxp[8][TT * 4 + 4];

    // ---- prepass: x-part of angles (incl. b_in); 2 timesteps/lane/element ----
    {
        const float* xeA = x + (long)eA * TT * 32;
        const float* xeB = x + (long)eB * TT * 32;
        const int t0i = lane * 2;
        float acc[2][2][4];
#pragma unroll
        for (int el = 0; el < 2; ++el)
#pragma unroll
            for (int i = 0; i < 2; ++i)
#pragma unroll
                for (int w = 0; w < 4; ++w) acc[el][i][w] = 0.f;
#pragma unroll
        for (int ch = 0; ch < 8; ++ch) {
            float4 wv[4];
#pragma unroll
            for (int w = 0; w < 4; ++w)
                wv[w] = *reinterpret_cast<const float4*>(&w_in[w * 40 + 8 + 4 * ch]);
#pragma unroll
            for (int el = 0; el < 2; ++el) {
                const float* xe = el ? xeB : xeA;
                float4 xv0 = *reinterpret_cast<const float4*>(&xe[t0i * 32 + 4 * ch]);
                float4 xv1 = *reinterpret_cast<const float4*>(&xe[(t0i + 1) * 32 + 4 * ch]);
#pragma unroll
                for (int w = 0; w < 4; ++w) {
                    acc[el][0][w] = fmaf(xv0.x, wv[w].x, acc[el][0][w]);
                    acc[el][0][w] = fmaf(xv0.y, wv[w].y, acc[el][0][w]);
                    acc[el][0][w] = fmaf(xv0.z, wv[w].z, acc[el][0][w]);
                    acc[el][0][w] = fmaf(xv0.w, wv[w].w, acc[el][0][w]);
                    acc[el][1][w] = fmaf(xv1.x, wv[w].x, acc[el][1][w]);
                    acc[el][1][w] = fmaf(xv1.y, wv[w].y, acc[el][1][w]);
                    acc[el][1][w] = fmaf(xv1.z, wv[w].z, acc[el][1][w]);
                    acc[el][1][w] = fmaf(xv1.w, wv[w].w, acc[el][1][w]);
                }
            }
        }
#pragma unroll
        for (int el = 0; el < 2; ++el)
#pragma unroll
            for (int i = 0; i < 2; ++i)
#pragma unroll
                for (int w = 0; w < 4; ++w)
                    sxp[wib * 2 + el][(t0i + i) * 4 + w] = acc[el][i][w] + __ldg(&b_in[w]);
    }
    __syncwarp();

    // ---- permuted h-projection weights: Whp[m] = W[(sub^m)&3][sub] ----
    float Whp[8];
#pragma unroll
    for (int m = 0; m < 8; ++m)
        Whp[m] = __ldg(&w_in[((sub ^ m) & 3) * 40 + sub]);

    // ---- own-gate closed-form coefficient vectors (shared by both elements) ----
    const float* wq = (g == 0) ? wq_f : (g == 1) ? wq_i : (g == 2) ? wq_u : wq_o;
    float cb[4], sb[4], cg_[4], sg_[4];
#pragma unroll
    for (int w = 0; w < 4; ++w) {
        float bv = __ldg(&wq[4 + w]); cb[w] = cosf(bv); sb[w] = sinf(bv);
        float cv = __ldg(&wq[w]);     cg_[w] = cosf(cv); sg_[w] = sinf(cv);
    }
    const float asc = (g == 2) ? 1.f : 0.5f;
    float Wo[4];
#pragma unroll
    for (int w = 0; w < 4; ++w) Wo[w] = asc * __ldg(&w_out[sub * 4 + w]);
    const float bo = asc * __ldg(&b_out[sub]);

    float V013[8], V023[8], V13[4], V02[4];
    {   // E0: wires {0,1,3}
        const int   p0[4] = {0, 7, 6, 1};
        const float K0[4] = {cb[1]*cb[2]*cb[3], cb[1]*cb[2]*sb[3],
                             sb[1]*sb[2]*cb[3], sb[1]*sb[2]*sb[3]};
#pragma unroll
        for (int b = 0; b < 8; ++b) {
            float s = 0.f;
#pragma unroll
            for (int t = 0; t < 4; ++t)
                s += K0[t] * fco(p0[t] & 1, b & 1, cg_[0], sg_[0])
                           * fco((p0[t] >> 1) & 1, (b >> 1) & 1, cg_[1], sg_[1])
                           * fco((p0[t] >> 2) & 1, (b >> 2) & 1, cg_[3], sg_[3]);
            V013[b] = Wo[0] * s;
        }
    }
    {   // E1: wires {0,2,3}
        const int   p1[2] = {0, 3};
        const float K1[2] = {cb[0]*cb[1], sb[0]*sb[1]};
#pragma unroll
        for (int b = 0; b < 8; ++b) {
            float s = 0.f;
#pragma unroll
            for (int t = 0; t < 2; ++t)
                s += K1[t] * fco(p1[t] & 1, b & 1, cg_[0], sg_[0])
                           * fco((p1[t] >> 1) & 1, (b >> 1) & 1, cg_[2], sg_[2])
                           * fco((p1[t] >> 2) & 1, (b >> 2) & 1, cg_[3], sg_[3]);
            V023[b] = Wo[1] * s;
        }
    }
    {   // E2: wires {1,3}
        const int   p2[2] = {0, 3};
        const float K2[2] = {cb[0]*cb[1]*cb[2], cb[0]*sb[1]*sb[2]};
#pragma unroll
        for (int b = 0; b < 4; ++b) {
            float s = 0.f;
#pragma unroll
            for (int t = 0; t < 2; ++t)
                s += K2[t] * fco(p2[t] & 1, b & 1, cg_[1], sg_[1])
                           * fco((p2[t] >> 1) & 1, (b >> 1) & 1, cg_[3], sg_[3]);
            V13[b] = Wo[2] * s;
        }
    }
    {   // E3: wires {0,2}
        const int   p3[4] = {0, 3, 2, 1};
        const float K3[4] = {cb[0]*cb[1]*cb[2]*cb[3], sb[0]*sb[1]*cb[2]*cb[3],
                             sb[0]*cb[1]*sb[2]*sb[3], cb[0]*sb[1]*sb[2]*sb[3]};
#pragma unroll
        for (int b = 0; b < 4; ++b) {
            float s = 0.f;
#pragma unroll
            for (int t = 0; t < 4; ++t)
                s += K3[t] * fco(p3[t] & 1, b & 1, cg_[0], sg_[0])
                           * fco((p3[t] >> 1) & 1, (b >> 1) & 1, cg_[2], sg_[2]);
            V02[b] = Wo[3] * s;
        }
    }

    float ccA = 0.f, hA = 0.f, ccB = 0.f, hB = 0.f;

#pragma unroll 1
    for (int t = 0; t < TT; ++t) {
        // S1 (dual): angle transpose-reduce, phases interleaved
        float xvA = sxp[slotA][t * 4 + (sub & 3)];
        float xvB = sxp[slotB][t * 4 + (sub & 3)];
        float redA = fmaf(hA, Whp[0], xvA);
        float redB = fmaf(hB, Whp[0], xvB);
#pragma unroll
        for (int m = 1; m < 8; ++m) {
            redA += sx(hA * Whp[m], m);
            redB += sx(hB * Whp[m], m);
        }

        // S2 (dual): sincos + share
        float msA, mcA, msB, mcB;
        __sincosf(redA, &msA, &mcA);
        __sincosf(redB, &msB, &mcB);
        float cYA[4], sYA[4], cYB[4], sYB[4];
#pragma unroll
        for (int w = 0; w < 4; ++w) {
            cYA[w] = __shfl_sync(FULL, mcA, b8 | w);
            sYA[w] = __shfl_sync(FULL, msA, b8 | w);
            cYB[w] = __shfl_sync(FULL, mcB, b8 | w);
            sYB[w] = __shfl_sync(FULL, msB, b8 | w);
        }

        // basis (dual)
        float p01A[4] = {cYA[0]*cYA[1], sYA[0]*cYA[1], cYA[0]*sYA[1], sYA[0]*sYA[1]};
        float p02A[4] = {cYA[0]*cYA[2], sYA[0]*cYA[2], cYA[0]*sYA[2], sYA[0]*sYA[2]};
        float p01B[4] = {cYB[0]*cYB[1], sYB[0]*cYB[1], cYB[0]*sYB[1], sYB[0]*sYB[1]};
        float p02B[4] = {cYB[0]*cYB[2], sYB[0]*cYB[2], cYB[0]*sYB[2], sYB[0]*sYB[2]};

        // dot (dual, Y3 factored): gv = bo + V02.p02 + cY3*A + sY3*B
        float aA0 = V013[0] * p01A[0], aA1 = V013[1] * p01A[1];
        float aB0 = V013[0] * p01B[0], aB1 = V013[1] * p01B[1];
        aA0 = fmaf(V013[2], p01A[2], aA0); aA1 = fmaf(V013[3], p01A[3], aA1);
        aB0 = fmaf(V013[2], p01B[2], aB0); aB1 = fmaf(V013[3], p01B[3], aB1);
        aA0 = fmaf(V023[0], p02A[0], aA0); aA1 = fmaf(V023[1], p02A[1], aA1);
        aB0 = fmaf(V023[0], p02B[0], aB0); aB1 = fmaf(V023[1], p02B[1], aB1);
        aA0 = fmaf(V023[2], p02A[2], aA0); aA1 = fmaf(V023[3], p02A[3], aA1);
        aB0 = fmaf(V023[2], p02B[2], aB0); aB1 = fmaf(V023[3], p02B[3], aB1);
        aA0 = fmaf(V13[0], cYA[1], aA0);   aA1 = fmaf(V13[1], sYA[1], aA1);
        aB0 = fmaf(V13[0], cYB[1], aB0);   aB1 = fmaf(V13[1], sYB[1], aB1);
        float AA = aA0 + aA1, AB = aB0 + aB1;

        float bA0 = V013[4] * p01A[0], bA1 = V013[5] * p01A[1];
        float bB0 = V013[4] * p01B[0], bB1 = V013[5] * p01B[1];
        bA0 = fmaf(V013[6], p01A[2], bA0); bA1 = fmaf(V013[7], p01A[3], bA1);
        bB0 = fmaf(V013[6], p01B[2], bB0); bB1 = fmaf(V013[7], p01B[3], bB1);
        bA0 = fmaf(V023[4], p02A[0], bA0); bA1 = fmaf(V023[5], p02A[1], bA1);
        bB0 = fmaf(V023[4], p02B[0], bB0); bB1 = fmaf(V023[5], p02B[1], bB1);
        bA0 = fmaf(V023[6], p02A[2], bA0); bA1 = fmaf(V023[7], p02A[3], bA1);
        bB0 = fmaf(V023[6], p02B[2], bB0); bB1 = fmaf(V023[7], p02B[3], bB1);
        bA0 = fmaf(V13[2], cYA[1], bA0);   bA1 = fmaf(V13[3], sYA[1], bA1);
        bB0 = fmaf(V13[2], cYB[1], bB0);   bB1 = fmaf(V13[3], sYB[1], bB1);
        float BA = bA0 + bA1, BB = bB0 + bB1;

        float gA0 = fmaf(V02[0], p02A[0], bo);
        float gB0 = fmaf(V02[0], p02B[0], bo);
        float gA1 = V02[1] * p02A[1];
        float gB1 = V02[1] * p02B[1];
        gA0 = fmaf(V02[2], p02A[2], gA0);
        gB0 = fmaf(V02[2], p02B[2], gB0);
        gA1 = fmaf(V02[3], p02A[3], gA1);
        gB1 = fmaf(V02[3], p02B[3], gB1);
        float gvA = fmaf(cYA[3], AA, fmaf(sYA[3], BA, gA0 + gA1));
        float gvB = fmaf(cYB[3], AB, fmaf(sYB[3], BB, gB0 + gB1));

        float actA = (g == 2) ? tanhap(gvA) : fmaf(0.5f, tanhap(gvA), 0.5f);
        float actB = (g == 2) ? tanhap(gvB) : fmaf(0.5f, tanhap(gvB), 0.5f);

        // S3 (dual): gather gates for own comp; cell updates
        float fvA = __shfl_sync(FULL, actA, sub);
        float fvB = __shfl_sync(FULL, actB, sub);
        float ivA = __shfl_sync(FULL, actA, sub + 8);
        float ivB = __shfl_sync(FULL, actB, sub + 8);
        float uvA = __shfl_sync(FULL, actA, sub + 16);
        float uvB = __shfl_sync(FULL, actB, sub + 16);
        float ovA = __shfl_sync(FULL, actA, sub + 24);
        float ovB = __shfl_sync(FULL, actB, sub + 24);

        ccA = fmaf(fvA, ccA, ivA * uvA);
        ccB = fmaf(fvB, ccB, ivB * uvB);
        hA = ovA * tanhap(ccA);
        hB = ovB * tanhap(ccB);
    }

    // ---- final projections ----
    const float wfc = __ldg(&w_fc[sub]);
    const float bfc = __ldg(&b_fc[0]);
    float pA = hA * wfc, pB = hB * wfc;
    pA += sx(pA, 1); pB += sx(pB, 1);
    pA += sx(pA, 2); pB += sx(pB, 2);
    pA += sx(pA, 4); pB += sx(pB, 4);
    if (lane == 0) {
        if (okA) out[eA] = pA + bfc;
        if (okB) out[eB] = pB + bfc;
    }
}

extern "C" void kernel_launch(void* const* d_in, const int* in_sizes, int n_in,
                              void* d_out, int out_size) {
    const float* x     = (const float*)d_in[0];
    const float* w_in  = (const float*)d_in[1];
    const float* b_in  = (const float*)d_in[2];
    const float* w_out = (const float*)d_in[3];
    const float* b_out = (const float*)d_in[4];
    const float* wq_f  = (const float*)d_in[5];
    const float* wq_i  = (const float*)d_in[6];
    const float* wq_u  = (const float*)d_in[7];
    const float* wq_o  = (const float*)d_in[8];
    const float* w_fc  = (const float*)d_in[9];
    const float* b_fc  = (const float*)d_in[10];

    int B = in_sizes[0] / (TT * 32);
    int blocks = (B + 7) / 8;              // 8 elements per 128-thread block
    qlstmcf32d<<<blocks, 128>>>(x, w_in, b_in, w_out, b_out,
                                wq_f, wq_i, wq_u, wq_o, w_fc, b_fc,
                                (float*)d_out, B);
}

// round 17
// speedup vs baseline: 1.1946x; 1.1946x over previous
#include <cuda_runtime.h>

#define TT 64
#define FULL 0xffffffffu

__device__ __forceinline__ float sx(float v, int m) { return __shfl_xor_sync(FULL, v, m); }
__device__ __forceinline__ float tanhap(float v) {
    float r; asm("tanh.approx.f32 %0, %1;" : "=f"(r) : "f"(v)); return r;
}
// basis coefficient: factor p (0:cos(alpha),1:sin(alpha)), basis bit b (0->cY,1->sY)
__device__ __forceinline__ float fco(int p, int b, float cg, float sg) {
    return p ? (b ? cg : sg) : (b ? -sg : cg);
}

// 16 lanes per element, 2 elements per warp.
// lane = e2*16 + g*4 + c ; lane owns comps {2c,2c+1} of gate g, computes E_c.
__global__ void __launch_bounds__(128)
qlstm16e(const float* __restrict__ x,
         const float* __restrict__ w_in,  const float* __restrict__ b_in,
         const float* __restrict__ w_out, const float* __restrict__ b_out,
         const float* __restrict__ wq_f,  const float* __restrict__ wq_i,
         const float* __restrict__ wq_u,  const float* __restrict__ wq_o,
         const float* __restrict__ w_fc,  const float* __restrict__ b_fc,
         float* __restrict__ out, int B)
{
    const int lane   = threadIdx.x & 31;
    const int wib    = threadIdx.x >> 5;       // warp in block (0..3)
    const int e2     = lane >> 4;
    const int lane16 = lane & 15;
    const int g      = lane16 >> 2;
    const int c      = lane16 & 3;
    const int b16    = lane & ~15;
    const int b4     = lane & ~3;
    const int j0 = 2 * c, j1 = 2 * c + 1;
    const int slot = wib * 2 + e2;
    int e = blockIdx.x * 8 + slot;
    const bool ok = (e < B);
    if (!ok) e = B - 1;

    __shared__ float sxp[8][TT * 4 + 4];

    // ---- prepass: x-part of angles (incl. b_in); 4 timesteps per lane ----
    {
        const float* xe = x + (long)e * TT * 32;
        const int t0i = lane16 * 4;
        float acc[4][4];
#pragma unroll
        for (int i = 0; i < 4; ++i)
#pragma unroll
            for (int w = 0; w < 4; ++w) acc[i][w] = 0.f;
#pragma unroll
        for (int ch = 0; ch < 8; ++ch) {
            float4 wv[4];
#pragma unroll
            for (int w = 0; w < 4; ++w)
                wv[w] = *reinterpret_cast<const float4*>(&w_in[w * 40 + 8 + 4 * ch]);
#pragma unroll
            for (int i = 0; i < 4; ++i) {
                float4 xv = *reinterpret_cast<const float4*>(&xe[(t0i + i) * 32 + 4 * ch]);
#pragma unroll
                for (int w = 0; w < 4; ++w) {
                    acc[i][w] = fmaf(xv.x, wv[w].x, acc[i][w]);
                    acc[i][w] = fmaf(xv.y, wv[w].y, acc[i][w]);
                    acc[i][w] = fmaf(xv.z, wv[w].z, acc[i][w]);
                    acc[i][w] = fmaf(xv.w, wv[w].w, acc[i][w]);
                }
            }
        }
#pragma unroll
        for (int i = 0; i < 4; ++i)
#pragma unroll
            for (int w = 0; w < 4; ++w)
                sxp[slot][(t0i + i) * 4 + w] = acc[i][w] + __ldg(&b_in[w]);
    }
    __syncwarp();

    // ---- transpose-reduce weights: Whp[m][k] = W[(c^m)&3][2c+k] ----
    float Whp[4][2];
#pragma unroll
    for (int m = 0; m < 4; ++m) {
        Whp[m][0] = __ldg(&w_in[((c ^ m) & 3) * 40 + j0]);
        Whp[m][1] = __ldg(&w_in[((c ^ m) & 3) * 40 + j1]);
    }

    // ---- own-gate raw expectation coefficients (no Wo factor) ----
    const float* wq = (g == 0) ? wq_f : (g == 1) ? wq_i : (g == 2) ? wq_u : wq_o;
    float cb[4], sb[4], cg_[4], sg_[4];
#pragma unroll
    for (int w = 0; w < 4; ++w) {
        float bv = __ldg(&wq[4 + w]); cb[w] = cosf(bv); sb[w] = sinf(bv);
        float cv = __ldg(&wq[w]);     cg_[w] = cosf(cv); sg_[w] = sinf(cv);
    }
    const float asc = (g == 2) ? 1.f : 0.5f;

    float U013[8], U023[8], U13[4], U02[4];
    {   // E0: wires {0,1,3}
        const int   p0[4] = {0, 7, 6, 1};
        const float K0[4] = {cb[1]*cb[2]*cb[3], cb[1]*cb[2]*sb[3],
                             sb[1]*sb[2]*cb[3], sb[1]*sb[2]*sb[3]};
#pragma unroll
        for (int b = 0; b < 8; ++b) {
            float s = 0.f;
#pragma unroll
            for (int t = 0; t < 4; ++t)
                s += K0[t] * fco(p0[t] & 1, b & 1, cg_[0], sg_[0])
                           * fco((p0[t] >> 1) & 1, (b >> 1) & 1, cg_[1], sg_[1])
                           * fco((p0[t] >> 2) & 1, (b >> 2) & 1, cg_[3], sg_[3]);
            U013[b] = s;
        }
    }
    {   // E1: wires {0,2,3}
        const int   p1[2] = {0, 3};
        const float K1[2] = {cb[0]*cb[1], sb[0]*sb[1]};
#pragma unroll
        for (int b = 0; b < 8; ++b) {
            float s = 0.f;
#pragma unroll
            for (int t = 0; t < 2; ++t)
                s += K1[t] * fco(p1[t] & 1, b & 1, cg_[0], sg_[0])
                           * fco((p1[t] >> 1) & 1, (b >> 1) & 1, cg_[2], sg_[2])
                           * fco((p1[t] >> 2) & 1, (b >> 2) & 1, cg_[3], sg_[3]);
            U023[b] = s;
        }
    }
    {   // E2: wires {1,3}
        const int   p2[2] = {0, 3};
        const float K2[2] = {cb[0]*cb[1]*cb[2], cb[0]*sb[1]*sb[2]};
#pragma unroll
        for (int b = 0; b < 4; ++b) {
            float s = 0.f;
#pragma unroll
            for (int t = 0; t < 2; ++t)
                s += K2[t] * fco(p2[t] & 1, b & 1, cg_[1], sg_[1])
                           * fco((p2[t] >> 1) & 1, (b >> 1) & 1, cg_[3], sg_[3]);
            U13[b] = s;
        }
    }
    {   // E3: wires {0,2}
        const int   p3[4] = {0, 3, 2, 1};
        const float K3[4] = {cb[0]*cb[1]*cb[2]*cb[3], sb[0]*sb[1]*cb[2]*cb[3],
                             sb[0]*cb[1]*sb[2]*sb[3], cb[0]*sb[1]*sb[2]*sb[3]};
#pragma unroll
        for (int b = 0; b < 4; ++b) {
            float s = 0.f;
#pragma unroll
            for (int t = 0; t < 4; ++t)
                s += K3[t] * fco(p3[t] & 1, b & 1, cg_[0], sg_[0])
                           * fco((p3[t] >> 1) & 1, (b >> 1) & 1, cg_[2], sg_[2]);
            U02[b] = s;
        }
    }

    // lane-specific dual 4-vectors for own E_c
    float W4[4], W5[4];
#pragma unroll
    for (int i = 0; i < 4; ++i) {
        W4[i] = (c == 0) ? U013[i] : (c == 1) ? U023[i]
              : (c == 2) ? ((i < 2) ? U13[i] : 0.f) : U02[i];
        W5[i] = (c == 0) ? U013[4 + i] : (c == 1) ? U023[4 + i]
              : (c == 2) ? ((i < 2) ? U13[2 + i] : 0.f) : 0.f;
    }
    // output projection rows (asc folded)
    float Wo2[2][4], bo2[2];
#pragma unroll
    for (int i = 0; i < 2; ++i) {
        bo2[i] = asc * __ldg(&b_out[j0 + i]);
#pragma unroll
        for (int w = 0; w < 4; ++w)
            Wo2[i][w] = asc * __ldg(&w_out[(j0 + i) * 4 + w]);
    }

    float cc0 = 0.f, cc1 = 0.f, h0 = 0.f, h1 = 0.f;

#pragma unroll 1
    for (int t = 0; t < TT; ++t) {
        // S1: angle transpose-reduce over 4 lanes (one stage)
        float xval = sxp[slot][t * 4 + c];
        float red = fmaf(h0, Whp[0][0], fmaf(h1, Whp[0][1], xval));
        red += sx(fmaf(h0, Whp[1][0], h1 * Whp[1][1]), 1);
        red += sx(fmaf(h0, Whp[2][0], h1 * Whp[2][1]), 2);
        red += sx(fmaf(h0, Whp[3][0], h1 * Whp[3][1]), 3);

        // S2: own sincos; share 4 wires within b4
        float mys, myc;
        __sincosf(red, &mys, &myc);
        float cY[4], sY[4];
#pragma unroll
        for (int w = 0; w < 4; ++w) {
            cY[w] = __shfl_sync(FULL, myc, b4 | w);
            sY[w] = __shfl_sync(FULL, mys, b4 | w);
        }

        // lane-selected basis quad q
        float p01[4] = {cY[0]*cY[1], sY[0]*cY[1], cY[0]*sY[1], sY[0]*sY[1]};
        float p02[4] = {cY[0]*cY[2], sY[0]*cY[2], cY[0]*sY[2], sY[0]*sY[2]};
        float q[4];
#pragma unroll
        for (int i = 0; i < 4; ++i) {
            float tq = (c == 0) ? p01[i] : p02[i];
            q[i] = (c == 2) ? ((i & 1) ? sY[1] : cY[1]) : tq;
        }

        // own E_c: dual 4-dot + Y3 combine (c==3 has no Y3 factor)
        float dA = fmaf(W4[0], q[0], W4[1] * q[1]);
        float dB = fmaf(W5[0], q[0], W5[1] * q[1]);
        dA = fmaf(W4[2], q[2], dA); dA = fmaf(W4[3], q[3], dA);
        dB = fmaf(W5[2], q[2], dB); dB = fmaf(W5[3], q[3], dB);
        float s1 = (c == 3) ? 1.f : cY[3];
        float s2 = (c == 3) ? 0.f : sY[3];
        float Eown = fmaf(s1, dA, s2 * dB);

        // S2b: share E within gate quad (wire order = c order)
        float Ew[4];
#pragma unroll
        for (int w = 0; w < 4; ++w)
            Ew[w] = __shfl_sync(FULL, Eown, b4 | w);

        // gate values for own 2 comps
        float gv0 = fmaf(Ew[0], Wo2[0][0], bo2[0]);
        float gv1 = fmaf(Ew[0], Wo2[1][0], bo2[1]);
        gv0 = fmaf(Ew[1], Wo2[0][1], gv0); gv1 = fmaf(Ew[1], Wo2[1][1], gv1);
        gv0 = fmaf(Ew[2], Wo2[0][2], gv0); gv1 = fmaf(Ew[2], Wo2[1][2], gv1);
        gv0 = fmaf(Ew[3], Wo2[0][3], gv0); gv1 = fmaf(Ew[3], Wo2[1][3], gv1);

        float act0 = (g == 2) ? tanhap(gv0) : fmaf(0.5f, tanhap(gv0), 0.5f);
        float act1 = (g == 2) ? tanhap(gv1) : fmaf(0.5f, tanhap(gv1), 0.5f);

        // S3: gather f,i,u,o for comps j0/j1 (within b16); cell update
        float fv0 = __shfl_sync(FULL, act0, b16 + c);
        float fv1 = __shfl_sync(FULL, act1, b16 + c);
        float iv0 = __shfl_sync(FULL, act0, b16 + 4 + c);
        float iv1 = __shfl_sync(FULL, act1, b16 + 4 + c);
        float uv0 = __shfl_sync(FULL, act0, b16 + 8 + c);
        float uv1 = __shfl_sync(FULL, act1, b16 + 8 + c);
        float ov0 = __shfl_sync(FULL, act0, b16 + 12 + c);
        float ov1 = __shfl_sync(FULL, act1, b16 + 12 + c);

        cc0 = fmaf(fv0, cc0, iv0 * uv0);
        cc1 = fmaf(fv1, cc1, iv1 * uv1);
        h0 = ov0 * tanhap(cc0);
        h1 = ov1 * tanhap(cc1);
    }

    // ---- final projection: sum over 4 lanes of a gate group ----
    float p = fmaf(h1, __ldg(&w_fc[j1]), h0 * __ldg(&w_fc[j0]));
    p += sx(p, 1);
    p += sx(p, 2);
    if (lane16 == 0 && ok) out[e] = p + __ldg(&b_fc[0]);
}

extern "C" void kernel_launch(void* const* d_in, const int* in_sizes, int n_in,
                              void* d_out, int out_size) {
    const float* x     = (const float*)d_in[0];
    const float* w_in  = (const float*)d_in[1];
    const float* b_in  = (const float*)d_in[2];
    const float* w_out = (const float*)d_in[3];
    const float* b_out = (const float*)d_in[4];
    const float* wq_f  = (const float*)d_in[5];
    const float* wq_i  = (const float*)d_in[6];
    const float* wq_u  = (const float*)d_in[7];
    const float* wq_o  = (const float*)d_in[8];
    const float* w_fc  = (const float*)d_in[9];
    const float* b_fc  = (const float*)d_in[10];

    int B = in_sizes[0] / (TT * 32);
    int blocks = (B + 7) / 8;              // 8 elements per 128-thread block
    qlstm16e<<<blocks, 128>>>(x, w_in, b_in, w_out, b_out,
                              wq_f, wq_i, wq_u, wq_o, w_fc, b_fc,
                              (float*)d_out, B);
}